// round 14
// baseline (speedup 1.0000x reference)
#include <cuda_runtime.h>
#include <mma.h>
#include <math.h>

using namespace nvcuda;

#define NN 50000
#define EE 1600000
#define E2T (EE + NN)
#define GG 512
#define NEG 0.2f
#define DMAX 1024

typedef unsigned long long u64;

// ---------------- f32x2 packed math (Blackwell) ----------------
__device__ __forceinline__ u64 pk2(float lo, float hi) {
    u64 r; asm("mov.b64 %0, {%1, %2};" : "=l"(r) : "f"(lo), "f"(hi)); return r;
}
__device__ __forceinline__ void upk2(u64 v, float& lo, float& hi) {
    asm("mov.b64 {%0, %1}, %2;" : "=f"(lo), "=f"(hi) : "l"(v));
}
__device__ __forceinline__ u64 fma2(u64 a, u64 b, u64 c) {
    u64 d; asm("fma.rn.f32x2 %0, %1, %2, %3;" : "=l"(d) : "l"(a), "l"(b), "l"(c)); return d;
}
__device__ __forceinline__ u64 add2(u64 a, u64 b) {
    u64 d; asm("add.rn.f32x2 %0, %1, %2;" : "=l"(d) : "l"(a), "l"(b)); return d;
}
__device__ __forceinline__ u64 mul2(u64 a, u64 b) {
    u64 d; asm("mul.rn.f32x2 %0, %1, %2;" : "=l"(d) : "l"(a), "l"(b)); return d;
}
__device__ __forceinline__ void pref_l2(const void* p) {
    asm volatile("prefetch.global.L2 [%0];" :: "l"(p));
}

// ---------------- scratch ----------------
__device__ float g_xlr1[(size_t)NN * 200];
__device__ float g_out1[(size_t)NN * 100];
__device__ float g_xlr2[(size_t)NN * 400];
__device__ float g_out2[(size_t)NN * 200];
__device__ float g_eac[(size_t)E2T * 18];
// combined int scratch: [cnt NN][cur NN][dh DMAX][dcur DMAX]  (single memset)
__device__ int   g_ints[2 * NN + 2 * DMAX];
__device__ int   g_off[NN + 1];
__device__ int   g_doff[DMAX];
__device__ int   g_csrc[E2T];
__device__ int   g_selfp[NN];
__device__ int   g_perm[NN];
__device__ float g_pool2[GG * 200];
__device__ float g_pool3[GG * 400];
__device__ float g_y1[GG * 200];
__device__ float g_y2[GG * 100];

// ---------------- CSR build ----------------
__global__ void k_hist(const int* __restrict__ ei, int* __restrict__ cnt) {
    int i = blockIdx.x * blockDim.x + threadIdx.x;
    if (i < EE) atomicAdd(&cnt[ei[EE + i]], 1);
    else if (i < EE + NN) atomicAdd(&cnt[i - EE], 1);
}

__global__ void k_scan(const int* __restrict__ cnt, int* __restrict__ off) {
    __shared__ int ssum[1024];
    int t = threadIdx.x;
    const int NPT = (NN + 1023) / 1024;
    int base = t * NPT;
    int local = 0;
    for (int i = 0; i < NPT; i++)
        if (base + i < NN) local += cnt[base + i];
    ssum[t] = local;
    __syncthreads();
    for (int o = 1; o < 1024; o <<= 1) {
        int v = (t >= o) ? ssum[t - o] : 0;
        __syncthreads();
        ssum[t] += v;
        __syncthreads();
    }
    int run = ssum[t] - local;
    for (int i = 0; i < NPT; i++) {
        int idx = base + i;
        if (idx < NN) { off[idx] = run; run += cnt[idx]; }
    }
    if (t == 1023) off[NN] = run;
}

// fused scatter: writes csrc + eac row (real edges) or selfp (self loops)
__global__ void k_scatter(const int* __restrict__ ei, const float* __restrict__ ea,
                          const int* __restrict__ off, int* __restrict__ cur,
                          int* __restrict__ csrc, float* __restrict__ eac,
                          int* __restrict__ selfp) {
    int e = blockIdx.x * blockDim.x + threadIdx.x;
    if (e >= E2T) return;
    int sn, dn;
    if (e < EE) { sn = ei[e]; dn = ei[EE + e]; }
    else        { sn = e - EE; dn = sn; }
    int p = off[dn] + atomicAdd(&cur[dn], 1);
    csrc[p] = sn;
    if (e < EE) {
        const float2* src = (const float2*)ea + (size_t)e * 9;
        float2* dst = (float2*)eac + (size_t)p * 9;
#pragma unroll
        for (int k = 0; k < 9; k++) dst[k] = src[k];
    } else {
        selfp[e - EE] = p;
    }
}

// thread-per-(node, float2 pair) loop-mean of incoming edge attrs
__global__ void k_loopattr(const int* __restrict__ off, const int* __restrict__ selfp,
                           float* __restrict__ eac) {
    int t = blockIdx.x * blockDim.x + threadIdx.x;
    if (t >= NN * 9) return;
    int n = t / 9, pr = t - n * 9;
    int start = off[n], end = off[n + 1];
    int sp = selfp[n];
    const float2* ep = (const float2*)eac;
    float2 acc = make_float2(0.f, 0.f);
    for (int i = start; i < end; i++) {
        if (i == sp) continue;
        float2 v = ep[(size_t)i * 9 + pr];
        acc.x += v.x; acc.y += v.y;
    }
    float inv = 1.0f / fmaxf((float)(end - start - 1), 1.0f);
    ((float2*)eac)[(size_t)sp * 9 + pr] = make_float2(acc.x * inv, acc.y * inv);
}

// ---------------- degree counting-sort (descending, degree from cnt) ----------------
__global__ void k_deghist(const int* __restrict__ cnt, int* __restrict__ dh) {
    int n = blockIdx.x * blockDim.x + threadIdx.x;
    if (n >= NN) return;
    int d = min(cnt[n], DMAX - 1);
    atomicAdd(&dh[d], 1);
}

__global__ void k_dscan(const int* __restrict__ dh, int* __restrict__ doff) {
    __shared__ int s[DMAX];
    int t = threadIdx.x;
    s[t] = dh[DMAX - 1 - t];
    __syncthreads();
    for (int o = 1; o < DMAX; o <<= 1) {
        int v = (t >= o) ? s[t - o] : 0;
        __syncthreads();
        s[t] += v;
        __syncthreads();
    }
    int excl = s[t] - dh[DMAX - 1 - t];
    doff[DMAX - 1 - t] = excl;
}

__global__ void k_dscatter(const int* __restrict__ cnt, const int* __restrict__ doff,
                           int* __restrict__ dcur, int* __restrict__ perm) {
    int n = blockIdx.x * blockDim.x + threadIdx.x;
    if (n >= NN) return;
    int d = min(cnt[n], DMAX - 1);
    int p = doff[d] + atomicAdd(&dcur[d], 1);
    perm[p] = n;
}

// ---------------- SIMT GEMM (FFN head) ----------------
__global__ void k_gemm(const float* __restrict__ A, const float* __restrict__ B,
                       const float* __restrict__ bias, float* __restrict__ Cm,
                       int M, int K, int N, int relu) {
    __shared__ float As[16][64];
    __shared__ float Bs[16][64];
    int bm = blockIdx.y * 64, bn = blockIdx.x * 64;
    int tid = threadIdx.x;
    int tx = tid & 15, ty = tid >> 4;
    float acc[4][4];
#pragma unroll
    for (int r = 0; r < 4; r++)
#pragma unroll
        for (int c = 0; c < 4; c++) acc[r][c] = 0.f;
    for (int k0 = 0; k0 < K; k0 += 16) {
        for (int l = tid; l < 64 * 16; l += 256) {
            int r = l >> 4, kk = l & 15;
            As[kk][r] = (bm + r < M && k0 + kk < K) ? A[(size_t)(bm + r) * K + k0 + kk] : 0.f;
        }
        for (int l = tid; l < 16 * 64; l += 256) {
            int kk = l >> 6, c = l & 63;
            Bs[kk][c] = (k0 + kk < K && bn + c < N) ? B[(size_t)(k0 + kk) * N + bn + c] : 0.f;
        }
        __syncthreads();
#pragma unroll
        for (int kk = 0; kk < 16; kk++) {
            float av[4], bv[4];
#pragma unroll
            for (int r = 0; r < 4; r++) av[r] = As[kk][ty * 4 + r];
#pragma unroll
            for (int c = 0; c < 4; c++) bv[c] = Bs[kk][tx * 4 + c];
#pragma unroll
            for (int r = 0; r < 4; r++)
#pragma unroll
                for (int c = 0; c < 4; c++) acc[r][c] += av[r] * bv[c];
        }
        __syncthreads();
    }
#pragma unroll
    for (int r = 0; r < 4; r++) {
        int row = bm + ty * 4 + r;
        if (row >= M) continue;
#pragma unroll
        for (int c = 0; c < 4; c++) {
            int col = bn + tx * 4 + c;
            if (col < N) {
                float v = acc[r][c] + bias[col];
                Cm[(size_t)row * N + col] = relu ? fmaxf(v, 0.f) : v;
            }
        }
    }
}

// ---------------- TF32 wmma fused xl/xr GEMM ----------------
__global__ __launch_bounds__(256)
void k_gemm2_tc(const float* __restrict__ A,
                const float* __restrict__ Bl, const float* __restrict__ Br,
                const float* __restrict__ bl, const float* __restrict__ br,
                float* __restrict__ Cm, int M, int K, int C) {
    __shared__ float As[64 * 16];
    __shared__ float Bs[16 * 72];
    __shared__ float Cs[64 * 68];
    const int N = 2 * C;
    int bm = blockIdx.y * 64, bn = blockIdx.x * 64;
    int tid = threadIdx.x;
    int w = tid >> 5;
    int wy = w >> 1, wx = w & 1;

    wmma::fragment<wmma::accumulator, 16, 16, 8, float> acc[2];
    wmma::fill_fragment(acc[0], 0.f);
    wmma::fill_fragment(acc[1], 0.f);

    for (int k0 = 0; k0 < K; k0 += 16) {
        for (int l = tid; l < 64 * 16; l += 256) {
            int r = l >> 4, kk = l & 15;
            As[r * 16 + kk] = (bm + r < M && k0 + kk < K) ? A[(size_t)(bm + r) * K + k0 + kk] : 0.f;
        }
        for (int l = tid; l < 16 * 64; l += 256) {
            int kk = l >> 6, c = l & 63;
            int cg = bn + c;
            float v = 0.f;
            if (k0 + kk < K && cg < N)
                v = (cg < C) ? Bl[(size_t)(k0 + kk) * C + cg]
                             : Br[(size_t)(k0 + kk) * C + cg - C];
            Bs[kk * 72 + c] = v;
        }
        __syncthreads();
#pragma unroll
        for (int k8 = 0; k8 < 16; k8 += 8) {
            wmma::fragment<wmma::matrix_a, 16, 16, 8, wmma::precision::tf32, wmma::row_major> af;
            wmma::load_matrix_sync(af, &As[(wy * 16) * 16 + k8], 16);
#pragma unroll
            for (int i = 0; i < af.num_elements; i++) af.x[i] = wmma::__float_to_tf32(af.x[i]);
#pragma unroll
            for (int t = 0; t < 2; t++) {
                wmma::fragment<wmma::matrix_b, 16, 16, 8, wmma::precision::tf32, wmma::row_major> bf;
                wmma::load_matrix_sync(bf, &Bs[k8 * 72 + wx * 32 + t * 16], 72);
#pragma unroll
                for (int i = 0; i < bf.num_elements; i++) bf.x[i] = wmma::__float_to_tf32(bf.x[i]);
                wmma::mma_sync(acc[t], af, bf, acc[t]);
            }
        }
        __syncthreads();
    }
#pragma unroll
    for (int t = 0; t < 2; t++)
        wmma::store_matrix_sync(&Cs[(wy * 16) * 68 + wx * 32 + t * 16], acc[t], 68, wmma::mem_row_major);
    __syncthreads();
    for (int l = tid; l < 64 * 64; l += 256) {
        int r = l >> 6, c = l & 63;
        int row = bm + r, col = bn + c;
        if (row < M && col < N) {
            float bb = (col < C) ? bl[col] : br[col - C];
            Cm[(size_t)row * N + col] = Cs[r * 68 + c] + bb;
        }
    }
}

// ---------------- fused GATv2, f32x2-packed channels + L2 prefetch ----------------
template <int C, int NC2, int U>
__global__ __launch_bounds__(256)
void k_gat(const int* __restrict__ off, const int* __restrict__ csrc,
           const int* __restrict__ perm, const float* __restrict__ eac,
           const float* __restrict__ We, const float* __restrict__ av,
           const float* __restrict__ xlr, const float* __restrict__ bias,
           float* __restrict__ out) {
    extern __shared__ float2 sWe2[];  // [18][32*NC2]
    for (int idx = threadIdx.x; idx < 18 * 32 * NC2; idx += blockDim.x) {
        int k = idx / (32 * NC2), pc = idx - k * (32 * NC2);
        int c0 = 2 * pc;
        float lo = (c0 < C) ? We[k * C + c0] : 0.f;
        float hi = (c0 + 1 < C) ? We[k * C + c0 + 1] : 0.f;
        sWe2[idx] = make_float2(lo, hi);
    }
    __syncthreads();

    int wid = (blockIdx.x * blockDim.x + threadIdx.x) >> 5;
    int lane = threadIdx.x & 31;
    if (wid >= NN) return;
    int n = perm[wid];

    float avlo[NC2], avhi[NC2];
    u64 xrr2[NC2], acc2[NC2];
    const float* xrbase = xlr + (size_t)n * 2 * C + C;
#pragma unroll
    for (int j = 0; j < NC2; j++) {
        int c0 = 2 * (lane + 32 * j);
        avlo[j] = (c0 < C) ? av[c0] : 0.f;
        avhi[j] = (c0 + 1 < C) ? av[c0 + 1] : 0.f;
        float2 xv = (c0 < C) ? *(const float2*)(xrbase + c0) : make_float2(0.f, 0.f);
        xrr2[j] = pk2(xv.x, xv.y);
        acc2[j] = pk2(0.f, 0.f);
    }
    float m = -3.0e38f, z = 0.f;
    int start = off[n], end = off[n + 1];
    int i = start;

    for (; i + U <= end; i += U) {
        if (lane == 0 && i + 2 * U <= end) pref_l2(csrc + i + U);
        if (lane < 2 && i + 2 * U <= end)
            pref_l2(eac + (size_t)(i + U) * 18 + lane * (U * 9));
        int s[U];
        float av_[U];
#pragma unroll
        for (int u = 0; u < U; u++) {
            s[u] = csrc[i + u];
            av_[u] = (lane < 18) ? eac[(size_t)(i + u) * 18 + lane] : 0.f;
        }
        u64 xv2[U][NC2], vv2[U][NC2];
#pragma unroll
        for (int u = 0; u < U; u++) {
            const float* p = xlr + (size_t)s[u] * 2 * C;
#pragma unroll
            for (int j = 0; j < NC2; j++) {
                int c0 = 2 * (lane + 32 * j);
                float2 xv = (c0 < C) ? *(const float2*)(p + c0) : make_float2(0.f, 0.f);
                xv2[u][j] = pk2(xv.x, xv.y);
                vv2[u][j] = add2(xv2[u][j], xrr2[j]);
            }
        }
#pragma unroll
        for (int k = 0; k < 18; k++) {
            u64 e2[U];
#pragma unroll
            for (int u = 0; u < U; u++) {
                float e = __shfl_sync(0xffffffffu, av_[u], k);
                e2[u] = pk2(e, e);
            }
#pragma unroll
            for (int j = 0; j < NC2; j++) {
                float2 wv = sWe2[k * 32 * NC2 + lane + 32 * j];
                u64 w2 = pk2(wv.x, wv.y);
#pragma unroll
                for (int u = 0; u < U; u++) vv2[u][j] = fma2(e2[u], w2, vv2[u][j]);
            }
        }
        float sc[U];
#pragma unroll
        for (int u = 0; u < U; u++) {
            float a_ = 0.f;
#pragma unroll
            for (int j = 0; j < NC2; j++) {
                float lo, hi;
                upk2(vv2[u][j], lo, hi);
                a_ += avlo[j] * ((lo > 0.f) ? lo : NEG * lo);
                a_ += avhi[j] * ((hi > 0.f) ? hi : NEG * hi);
            }
            sc[u] = a_;
        }
#pragma unroll
        for (int o = 16; o; o >>= 1)
#pragma unroll
            for (int u = 0; u < U; u++) sc[u] += __shfl_xor_sync(0xffffffffu, sc[u], o);
        float newm = m;
#pragma unroll
        for (int u = 0; u < U; u++) newm = fmaxf(newm, sc[u]);
        float scale = __expf(m - newm);
        float wgt[U];
        float zadd = 0.f;
#pragma unroll
        for (int u = 0; u < U; u++) { wgt[u] = __expf(sc[u] - newm); zadd += wgt[u]; }
        z = z * scale + zadd;
        u64 scale2 = pk2(scale, scale);
        u64 wgt2[U];
#pragma unroll
        for (int u = 0; u < U; u++) wgt2[u] = pk2(wgt[u], wgt[u]);
#pragma unroll
        for (int j = 0; j < NC2; j++) {
            u64 a_ = mul2(acc2[j], scale2);
#pragma unroll
            for (int u = 0; u < U; u++) a_ = fma2(wgt2[u], xv2[u][j], a_);
            acc2[j] = a_;
        }
        m = newm;
    }
    for (; i < end; i++) {   // tail
        int s0 = csrc[i];
        float a0 = (lane < 18) ? eac[(size_t)i * 18 + lane] : 0.f;
        const float* p0 = xlr + (size_t)s0 * 2 * C;
        u64 x2[NC2], v2[NC2];
#pragma unroll
        for (int j = 0; j < NC2; j++) {
            int c0 = 2 * (lane + 32 * j);
            float2 xv = (c0 < C) ? *(const float2*)(p0 + c0) : make_float2(0.f, 0.f);
            x2[j] = pk2(xv.x, xv.y);
            v2[j] = add2(x2[j], xrr2[j]);
        }
#pragma unroll
        for (int k = 0; k < 18; k++) {
            float e = __shfl_sync(0xffffffffu, a0, k);
            u64 e2 = pk2(e, e);
#pragma unroll
            for (int j = 0; j < NC2; j++) {
                float2 wv = sWe2[k * 32 * NC2 + lane + 32 * j];
                v2[j] = fma2(e2, pk2(wv.x, wv.y), v2[j]);
            }
        }
        float sc0 = 0.f;
#pragma unroll
        for (int j = 0; j < NC2; j++) {
            float lo, hi;
            upk2(v2[j], lo, hi);
            sc0 += avlo[j] * ((lo > 0.f) ? lo : NEG * lo);
            sc0 += avhi[j] * ((hi > 0.f) ? hi : NEG * hi);
        }
#pragma unroll
        for (int o = 16; o; o >>= 1) sc0 += __shfl_xor_sync(0xffffffffu, sc0, o);
        float newm = fmaxf(m, sc0);
        float scale = __expf(m - newm);
        float w0 = __expf(sc0 - newm);
        z = z * scale + w0;
        u64 scale2 = pk2(scale, scale);
        u64 w02 = pk2(w0, w0);
#pragma unroll
        for (int j = 0; j < NC2; j++)
            acc2[j] = fma2(w02, x2[j], mul2(acc2[j], scale2));
        m = newm;
    }
    float invz = __fdividef(1.0f, z);
#pragma unroll
    for (int j = 0; j < NC2; j++) {
        int c0 = 2 * (lane + 32 * j);
        if (c0 < C) {
            float lo, hi;
            upk2(acc2[j], lo, hi);
            float2 o;
            o.x = fmaxf(lo * invz + bias[c0], 0.f);
            o.y = fmaxf(hi * invz + bias[c0 + 1], 0.f);
            *(float2*)(out + (size_t)n * C + c0) = o;
        }
    }
}

// ---------------- atomic-free mean pool (batch_ids sorted) ----------------
__global__ void k_pool(const float* __restrict__ h, const int* __restrict__ bid,
                       float* __restrict__ pool) {
    int g = blockIdx.x;
    __shared__ int slo, shi;
    if (threadIdx.x == 0) {
        int lo = 0, hi = NN;
        while (lo < hi) { int mid = (lo + hi) >> 1; if (bid[mid] < g) lo = mid + 1; else hi = mid; }
        slo = lo;
        int lo2 = lo; hi = NN;
        while (lo2 < hi) { int mid = (lo2 + hi) >> 1; if (bid[mid] < g + 1) lo2 = mid + 1; else hi = mid; }
        shi = lo2;
    }
    __syncthreads();
    int lo = slo, hi = shi;
    float inv = 1.0f / (float)max(hi - lo, 1);
    for (int c = threadIdx.x; c < 200; c += blockDim.x) {
        float sum = 0.f;
        for (int nn = lo; nn < hi; nn++) sum += h[(size_t)nn * 200 + c];
        pool[g * 200 + c] = sum * inv;
    }
}

// ---------------- launch ----------------
extern "C" void kernel_launch(void* const* d_in, const int* in_sizes, int n_in,
                              void* d_out, int out_size) {
    const float* x   = (const float*)d_in[0];
    const int*   ei  = (const int*)d_in[1];
    const float* ea  = (const float*)d_in[2];
    const int*   bid = (const int*)d_in[3];
    const float* W1l = (const float*)d_in[4];
    const float* b1l = (const float*)d_in[5];
    const float* W1r = (const float*)d_in[6];
    const float* b1r = (const float*)d_in[7];
    const float* W1e = (const float*)d_in[8];
    const float* a1  = (const float*)d_in[9];
    const float* c1  = (const float*)d_in[10];
    const float* W2l = (const float*)d_in[11];
    const float* b2l = (const float*)d_in[12];
    const float* W2r = (const float*)d_in[13];
    const float* b2r = (const float*)d_in[14];
    const float* W2e = (const float*)d_in[15];
    const float* a2  = (const float*)d_in[16];
    const float* c2  = (const float*)d_in[17];
    const float* W3  = (const float*)d_in[18];
    const float* b3  = (const float*)d_in[19];
    const float* F1  = (const float*)d_in[20];
    const float* bf1 = (const float*)d_in[21];
    const float* F2  = (const float*)d_in[22];
    const float* bf2 = (const float*)d_in[23];
    const float* F3  = (const float*)d_in[24];
    const float* bf3 = (const float*)d_in[25];

    float *xlr1, *out1, *xlr2, *out2, *eac, *pool2, *pool3, *y1, *y2;
    int *ints, *off, *doff, *csrc, *selfp, *perm;
    cudaGetSymbolAddress((void**)&xlr1,  g_xlr1);
    cudaGetSymbolAddress((void**)&out1,  g_out1);
    cudaGetSymbolAddress((void**)&xlr2,  g_xlr2);
    cudaGetSymbolAddress((void**)&out2,  g_out2);
    cudaGetSymbolAddress((void**)&eac,   g_eac);
    cudaGetSymbolAddress((void**)&ints,  g_ints);
    cudaGetSymbolAddress((void**)&off,   g_off);
    cudaGetSymbolAddress((void**)&doff,  g_doff);
    cudaGetSymbolAddress((void**)&csrc,  g_csrc);
    cudaGetSymbolAddress((void**)&selfp, g_selfp);
    cudaGetSymbolAddress((void**)&perm,  g_perm);
    cudaGetSymbolAddress((void**)&pool2, g_pool2);
    cudaGetSymbolAddress((void**)&pool3, g_pool3);
    cudaGetSymbolAddress((void**)&y1,    g_y1);
    cudaGetSymbolAddress((void**)&y2,    g_y2);

    int* cnt  = ints;
    int* cur  = ints + NN;
    int* dh   = ints + 2 * NN;
    int* dcur = ints + 2 * NN + DMAX;

    static cudaStream_t s1 = nullptr, s2 = nullptr;
    static cudaEvent_t evFork = nullptr, evCsr = nullptr, evDeg = nullptr, evHist = nullptr;
    if (!s1) {
        cudaStreamCreateWithFlags(&s1, cudaStreamNonBlocking);
        cudaStreamCreateWithFlags(&s2, cudaStreamNonBlocking);
        cudaEventCreateWithFlags(&evFork, cudaEventDisableTiming);
        cudaEventCreateWithFlags(&evCsr, cudaEventDisableTiming);
        cudaEventCreateWithFlags(&evDeg, cudaEventDisableTiming);
        cudaEventCreateWithFlags(&evHist, cudaEventDisableTiming);
    }

    const int T = 256;

    // ---- fork: CSR chain on s1, degree-sort on s2, gemm L1 on default ----
    cudaEventRecord(evFork, 0);
    cudaStreamWaitEvent(s1, evFork, 0);

    // s1: CSR build (fused scatter + eac gather)
    cudaMemsetAsync(ints, 0, (2 * NN + 2 * DMAX) * sizeof(int), s1);
    k_hist<<<(EE + NN + T - 1) / T, T, 0, s1>>>(ei, cnt);
    cudaEventRecord(evHist, s1);
    k_scan<<<1, 1024, 0, s1>>>(cnt, off);
    k_scatter<<<(E2T + T - 1) / T, T, 0, s1>>>(ei, ea, off, cur, csrc, eac, selfp);
    k_loopattr<<<(NN * 9 + T - 1) / T, T, 0, s1>>>(off, selfp, eac);
    cudaEventRecord(evCsr, s1);

    // s2: degree sort from cnt (overlaps scan/scatter)
    cudaStreamWaitEvent(s2, evHist, 0);
    k_deghist<<<(NN + T - 1) / T, T, 0, s2>>>(cnt, dh);
    k_dscan<<<1, DMAX, 0, s2>>>(dh, doff);
    k_dscatter<<<(NN + T - 1) / T, T, 0, s2>>>(cnt, doff, dcur, perm);
    cudaEventRecord(evDeg, s2);

    // default stream: layer-1 GEMM (independent of CSR)
    {
        dim3 g((200 + 63) / 64, (NN + 63) / 64);
        k_gemm2_tc<<<g, 256>>>(x, W1l, W1r, b1l, b1r, xlr1, NN, 16, 100);
    }

    // join
    cudaStreamWaitEvent(0, evCsr, 0);
    cudaStreamWaitEvent(0, evDeg, 0);

    // --- layer 1 GAT (256-thread blocks, low reg pressure) ---
    k_gat<100, 2, 8><<<(NN + 7) / 8, 256, 18 * 64 * sizeof(float2)>>>(
        off, csrc, perm, eac, W1e, a1, xlr1, c1, out1);

    // --- layer 2 ---
    {
        dim3 g((400 + 63) / 64, (NN + 63) / 64);
        k_gemm2_tc<<<g, 256>>>(out1, W2l, W2r, b2l, b2r, xlr2, NN, 100, 200);
    }
    // 128-thread blocks: high-reg kernel packs more blocks/SM -> more warps in flight
    k_gat<200, 4, 4><<<(NN + 3) / 4, 128, 18 * 128 * sizeof(float2)>>>(
        off, csrc, perm, eac, W2e, a2, xlr2, c2, out2);

    // --- mean pool, then 200->400 ---
    k_pool<<<GG, 256>>>(out2, bid, pool2);
    {
        dim3 g((400 + 63) / 64, (GG + 63) / 64);
        k_gemm<<<g, 256>>>(pool2, W3, b3, pool3, GG, 200, 400, 0);
    }

    // --- FFN head ---
    {
        dim3 g((200 + 63) / 64, (GG + 63) / 64);
        k_gemm<<<g, 256>>>(pool3, F1, bf1, y1, GG, 400, 200, 1);
    }
    {
        dim3 g((100 + 63) / 64, (GG + 63) / 64);
        k_gemm<<<g, 256>>>(y1, F2, bf2, y2, GG, 200, 100, 1);
    }
    {
        dim3 g((100 + 63) / 64, (GG + 63) / 64);
        k_gemm<<<g, 256>>>(y2, F3, bf3, (float*)d_out, GG, 100, 100, 0);
    }
}

// round 15
// speedup vs baseline: 1.0393x; 1.0393x over previous
#include <cuda_runtime.h>
#include <mma.h>
#include <math.h>

using namespace nvcuda;

#define NN 50000
#define EE 1600000
#define E2T (EE + NN)
#define GG 512
#define NEG 0.2f
#define DMAX 1024

typedef unsigned long long u64;

// ---------------- f32x2 packed math (Blackwell) ----------------
__device__ __forceinline__ u64 pk2(float lo, float hi) {
    u64 r; asm("mov.b64 %0, {%1, %2};" : "=l"(r) : "f"(lo), "f"(hi)); return r;
}
__device__ __forceinline__ void upk2(u64 v, float& lo, float& hi) {
    asm("mov.b64 {%0, %1}, %2;" : "=f"(lo), "=f"(hi) : "l"(v));
}
__device__ __forceinline__ u64 fma2(u64 a, u64 b, u64 c) {
    u64 d; asm("fma.rn.f32x2 %0, %1, %2, %3;" : "=l"(d) : "l"(a), "l"(b), "l"(c)); return d;
}
__device__ __forceinline__ u64 add2(u64 a, u64 b) {
    u64 d; asm("add.rn.f32x2 %0, %1, %2;" : "=l"(d) : "l"(a), "l"(b)); return d;
}
__device__ __forceinline__ u64 mul2(u64 a, u64 b) {
    u64 d; asm("mul.rn.f32x2 %0, %1, %2;" : "=l"(d) : "l"(a), "l"(b)); return d;
}
__device__ __forceinline__ void pref_l2(const void* p) {
    asm volatile("prefetch.global.L2 [%0];" :: "l"(p));
}

// ---------------- scratch ----------------
__device__ float g_xlr1[(size_t)NN * 200];
__device__ float g_out1[(size_t)NN * 100];
__device__ float g_xlr2[(size_t)NN * 400];
__device__ float g_out2[(size_t)NN * 200];
__device__ float g_eac[(size_t)E2T * 18];
// combined int scratch: [cnt NN][cur NN][dh DMAX][dcur DMAX]  (single memset)
__device__ int   g_ints[2 * NN + 2 * DMAX];
__device__ int   g_off[NN + 1];
__device__ int   g_doff[DMAX];
__device__ int   g_csrc[E2T];
__device__ int   g_pos[E2T];
__device__ int   g_perm[NN];
__device__ float g_pool2[GG * 200];
__device__ float g_pool3[GG * 400];
__device__ float g_y1[GG * 200];
__device__ float g_y2[GG * 100];

// ---------------- CSR build ----------------
__global__ void k_hist(const int* __restrict__ ei, int* __restrict__ cnt) {
    int i = blockIdx.x * blockDim.x + threadIdx.x;
    if (i < EE) atomicAdd(&cnt[ei[EE + i]], 1);
    else if (i < EE + NN) atomicAdd(&cnt[i - EE], 1);
}

__global__ void k_scan(const int* __restrict__ cnt, int* __restrict__ off) {
    __shared__ int ssum[1024];
    int t = threadIdx.x;
    const int NPT = (NN + 1023) / 1024;
    int base = t * NPT;
    int local = 0;
    for (int i = 0; i < NPT; i++)
        if (base + i < NN) local += cnt[base + i];
    ssum[t] = local;
    __syncthreads();
    for (int o = 1; o < 1024; o <<= 1) {
        int v = (t >= o) ? ssum[t - o] : 0;
        __syncthreads();
        ssum[t] += v;
        __syncthreads();
    }
    int run = ssum[t] - local;
    for (int i = 0; i < NPT; i++) {
        int idx = base + i;
        if (idx < NN) { off[idx] = run; run += cnt[idx]; }
    }
    if (t == 1023) off[NN] = run;
}

__global__ void k_scatter(const int* __restrict__ ei, const int* __restrict__ off,
                          int* __restrict__ cur, int* __restrict__ csrc,
                          int* __restrict__ pos) {
    int e = blockIdx.x * blockDim.x + threadIdx.x;
    if (e >= E2T) return;
    int sn, dn;
    if (e < EE) { sn = ei[e]; dn = ei[EE + e]; }
    else        { sn = e - EE; dn = sn; }
    int p = off[dn] + atomicAdd(&cur[dn], 1);
    csrc[p] = sn;
    pos[e] = p;
}

__global__ void k_eagather(const float* __restrict__ ea, const int* __restrict__ pos,
                           float* __restrict__ eac) {
    int i = blockIdx.x * blockDim.x + threadIdx.x;
    if (i >= EE * 9) return;
    int e = i / 9, k = i - e * 9;
    float2 v = ((const float2*)ea)[i];
    ((float2*)eac)[(size_t)pos[e] * 9 + k] = v;
}

// thread-per-(node, float2 pair) loop-mean of incoming edge attrs
__global__ void k_loopattr(const int* __restrict__ off, const int* __restrict__ pos,
                           float* __restrict__ eac) {
    int t = blockIdx.x * blockDim.x + threadIdx.x;
    if (t >= NN * 9) return;
    int n = t / 9, pr = t - n * 9;
    int start = off[n], end = off[n + 1];
    int selfpos = pos[EE + n];
    const float2* ep = (const float2*)eac;
    float2 acc = make_float2(0.f, 0.f);
    for (int i = start; i < end; i++) {
        if (i == selfpos) continue;
        float2 v = ep[(size_t)i * 9 + pr];
        acc.x += v.x; acc.y += v.y;
    }
    float inv = 1.0f / fmaxf((float)(end - start - 1), 1.0f);
    ((float2*)eac)[(size_t)selfpos * 9 + pr] = make_float2(acc.x * inv, acc.y * inv);
}

// ---------------- degree counting-sort (descending) ----------------
__global__ void k_deghist(const int* __restrict__ off, int* __restrict__ dh) {
    int n = blockIdx.x * blockDim.x + threadIdx.x;
    if (n >= NN) return;
    int d = min(off[n + 1] - off[n], DMAX - 1);
    atomicAdd(&dh[d], 1);
}

__global__ void k_dscan(const int* __restrict__ dh, int* __restrict__ doff) {
    __shared__ int s[DMAX];
    int t = threadIdx.x;
    s[t] = dh[DMAX - 1 - t];
    __syncthreads();
    for (int o = 1; o < DMAX; o <<= 1) {
        int v = (t >= o) ? s[t - o] : 0;
        __syncthreads();
        s[t] += v;
        __syncthreads();
    }
    int excl = s[t] - dh[DMAX - 1 - t];
    doff[DMAX - 1 - t] = excl;
}

__global__ void k_dscatter(const int* __restrict__ off, const int* __restrict__ doff,
                           int* __restrict__ dcur, int* __restrict__ perm) {
    int n = blockIdx.x * blockDim.x + threadIdx.x;
    if (n >= NN) return;
    int d = min(off[n + 1] - off[n], DMAX - 1);
    int p = doff[d] + atomicAdd(&dcur[d], 1);
    perm[p] = n;
}

// ---------------- SIMT GEMM (FFN head) ----------------
__global__ void k_gemm(const float* __restrict__ A, const float* __restrict__ B,
                       const float* __restrict__ bias, float* __restrict__ Cm,
                       int M, int K, int N, int relu) {
    __shared__ float As[16][64];
    __shared__ float Bs[16][64];
    int bm = blockIdx.y * 64, bn = blockIdx.x * 64;
    int tid = threadIdx.x;
    int tx = tid & 15, ty = tid >> 4;
    float acc[4][4];
#pragma unroll
    for (int r = 0; r < 4; r++)
#pragma unroll
        for (int c = 0; c < 4; c++) acc[r][c] = 0.f;
    for (int k0 = 0; k0 < K; k0 += 16) {
        for (int l = tid; l < 64 * 16; l += 256) {
            int r = l >> 4, kk = l & 15;
            As[kk][r] = (bm + r < M && k0 + kk < K) ? A[(size_t)(bm + r) * K + k0 + kk] : 0.f;
        }
        for (int l = tid; l < 16 * 64; l += 256) {
            int kk = l >> 6, c = l & 63;
            Bs[kk][c] = (k0 + kk < K && bn + c < N) ? B[(size_t)(k0 + kk) * N + bn + c] : 0.f;
        }
        __syncthreads();
#pragma unroll
        for (int kk = 0; kk < 16; kk++) {
            float av[4], bv[4];
#pragma unroll
            for (int r = 0; r < 4; r++) av[r] = As[kk][ty * 4 + r];
#pragma unroll
            for (int c = 0; c < 4; c++) bv[c] = Bs[kk][tx * 4 + c];
#pragma unroll
            for (int r = 0; r < 4; r++)
#pragma unroll
                for (int c = 0; c < 4; c++) acc[r][c] += av[r] * bv[c];
        }
        __syncthreads();
    }
#pragma unroll
    for (int r = 0; r < 4; r++) {
        int row = bm + ty * 4 + r;
        if (row >= M) continue;
#pragma unroll
        for (int c = 0; c < 4; c++) {
            int col = bn + tx * 4 + c;
            if (col < N) {
                float v = acc[r][c] + bias[col];
                Cm[(size_t)row * N + col] = relu ? fmaxf(v, 0.f) : v;
            }
        }
    }
}

// ---------------- TF32 wmma fused xl/xr GEMM ----------------
__global__ __launch_bounds__(256)
void k_gemm2_tc(const float* __restrict__ A,
                const float* __restrict__ Bl, const float* __restrict__ Br,
                const float* __restrict__ bl, const float* __restrict__ br,
                float* __restrict__ Cm, int M, int K, int C) {
    __shared__ float As[64 * 16];
    __shared__ float Bs[16 * 72];
    __shared__ float Cs[64 * 68];
    const int N = 2 * C;
    int bm = blockIdx.y * 64, bn = blockIdx.x * 64;
    int tid = threadIdx.x;
    int w = tid >> 5;
    int wy = w >> 1, wx = w & 1;

    wmma::fragment<wmma::accumulator, 16, 16, 8, float> acc[2];
    wmma::fill_fragment(acc[0], 0.f);
    wmma::fill_fragment(acc[1], 0.f);

    for (int k0 = 0; k0 < K; k0 += 16) {
        for (int l = tid; l < 64 * 16; l += 256) {
            int r = l >> 4, kk = l & 15;
            As[r * 16 + kk] = (bm + r < M && k0 + kk < K) ? A[(size_t)(bm + r) * K + k0 + kk] : 0.f;
        }
        for (int l = tid; l < 16 * 64; l += 256) {
            int kk = l >> 6, c = l & 63;
            int cg = bn + c;
            float v = 0.f;
            if (k0 + kk < K && cg < N)
                v = (cg < C) ? Bl[(size_t)(k0 + kk) * C + cg]
                             : Br[(size_t)(k0 + kk) * C + cg - C];
            Bs[kk * 72 + c] = v;
        }
        __syncthreads();
#pragma unroll
        for (int k8 = 0; k8 < 16; k8 += 8) {
            wmma::fragment<wmma::matrix_a, 16, 16, 8, wmma::precision::tf32, wmma::row_major> af;
            wmma::load_matrix_sync(af, &As[(wy * 16) * 16 + k8], 16);
#pragma unroll
            for (int i = 0; i < af.num_elements; i++) af.x[i] = wmma::__float_to_tf32(af.x[i]);
#pragma unroll
            for (int t = 0; t < 2; t++) {
                wmma::fragment<wmma::matrix_b, 16, 16, 8, wmma::precision::tf32, wmma::row_major> bf;
                wmma::load_matrix_sync(bf, &Bs[k8 * 72 + wx * 32 + t * 16], 72);
#pragma unroll
                for (int i = 0; i < bf.num_elements; i++) bf.x[i] = wmma::__float_to_tf32(bf.x[i]);
                wmma::mma_sync(acc[t], af, bf, acc[t]);
            }
        }
        __syncthreads();
    }
#pragma unroll
    for (int t = 0; t < 2; t++)
        wmma::store_matrix_sync(&Cs[(wy * 16) * 68 + wx * 32 + t * 16], acc[t], 68, wmma::mem_row_major);
    __syncthreads();
    for (int l = tid; l < 64 * 64; l += 256) {
        int r = l >> 6, c = l & 63;
        int row = bm + r, col = bn + c;
        if (row < M && col < N) {
            float bb = (col < C) ? bl[col] : br[col - C];
            Cm[(size_t)row * N + col] = Cs[r * 68 + c] + bb;
        }
    }
}

// ---------------- fused GATv2, f32x2-packed channels + L2 prefetch ----------------
template <int C, int NC2, int U>
__global__ __launch_bounds__(256)
void k_gat(const int* __restrict__ off, const int* __restrict__ csrc,
           const int* __restrict__ perm, const float* __restrict__ eac,
           const float* __restrict__ We, const float* __restrict__ av,
           const float* __restrict__ xlr, const float* __restrict__ bias,
           float* __restrict__ out) {
    extern __shared__ float2 sWe2[];  // [18][32*NC2]
    for (int idx = threadIdx.x; idx < 18 * 32 * NC2; idx += blockDim.x) {
        int k = idx / (32 * NC2), pc = idx - k * (32 * NC2);
        int c0 = 2 * pc;
        float lo = (c0 < C) ? We[k * C + c0] : 0.f;
        float hi = (c0 + 1 < C) ? We[k * C + c0 + 1] : 0.f;
        sWe2[idx] = make_float2(lo, hi);
    }
    __syncthreads();

    int wid = (blockIdx.x * blockDim.x + threadIdx.x) >> 5;
    int lane = threadIdx.x & 31;
    if (wid >= NN) return;
    int n = perm[wid];

    float avlo[NC2], avhi[NC2];
    u64 xrr2[NC2], acc2[NC2];
    const float* xrbase = xlr + (size_t)n * 2 * C + C;
#pragma unroll
    for (int j = 0; j < NC2; j++) {
        int c0 = 2 * (lane + 32 * j);
        avlo[j] = (c0 < C) ? av[c0] : 0.f;
        avhi[j] = (c0 + 1 < C) ? av[c0 + 1] : 0.f;
        float2 xv = (c0 < C) ? *(const float2*)(xrbase + c0) : make_float2(0.f, 0.f);
        xrr2[j] = pk2(xv.x, xv.y);
        acc2[j] = pk2(0.f, 0.f);
    }
    float m = -3.0e38f, z = 0.f;
    int start = off[n], end = off[n + 1];
    int i = start;

    for (; i + U <= end; i += U) {
        if (lane == 0 && i + 2 * U <= end) pref_l2(csrc + i + U);
        if (lane < 2 && i + 2 * U <= end)
            pref_l2(eac + (size_t)(i + U) * 18 + lane * (U * 9));
        int s[U];
        float av_[U];
#pragma unroll
        for (int u = 0; u < U; u++) {
            s[u] = csrc[i + u];
            av_[u] = (lane < 18) ? eac[(size_t)(i + u) * 18 + lane] : 0.f;
        }
        u64 xv2[U][NC2], vv2[U][NC2];
#pragma unroll
        for (int u = 0; u < U; u++) {
            const float* p = xlr + (size_t)s[u] * 2 * C;
#pragma unroll
            for (int j = 0; j < NC2; j++) {
                int c0 = 2 * (lane + 32 * j);
                float2 xv = (c0 < C) ? *(const float2*)(p + c0) : make_float2(0.f, 0.f);
                xv2[u][j] = pk2(xv.x, xv.y);
                vv2[u][j] = add2(xv2[u][j], xrr2[j]);
            }
        }
#pragma unroll
        for (int k = 0; k < 18; k++) {
            u64 e2[U];
#pragma unroll
            for (int u = 0; u < U; u++) {
                float e = __shfl_sync(0xffffffffu, av_[u], k);
                e2[u] = pk2(e, e);
            }
#pragma unroll
            for (int j = 0; j < NC2; j++) {
                float2 wv = sWe2[k * 32 * NC2 + lane + 32 * j];
                u64 w2 = pk2(wv.x, wv.y);
#pragma unroll
                for (int u = 0; u < U; u++) vv2[u][j] = fma2(e2[u], w2, vv2[u][j]);
            }
        }
        float sc[U];
#pragma unroll
        for (int u = 0; u < U; u++) {
            float a_ = 0.f;
#pragma unroll
            for (int j = 0; j < NC2; j++) {
                float lo, hi;
                upk2(vv2[u][j], lo, hi);
                a_ += avlo[j] * ((lo > 0.f) ? lo : NEG * lo);
                a_ += avhi[j] * ((hi > 0.f) ? hi : NEG * hi);
            }
            sc[u] = a_;
        }
#pragma unroll
        for (int o = 16; o; o >>= 1)
#pragma unroll
            for (int u = 0; u < U; u++) sc[u] += __shfl_xor_sync(0xffffffffu, sc[u], o);
        float newm = m;
#pragma unroll
        for (int u = 0; u < U; u++) newm = fmaxf(newm, sc[u]);
        float scale = __expf(m - newm);
        float wgt[U];
        float zadd = 0.f;
#pragma unroll
        for (int u = 0; u < U; u++) { wgt[u] = __expf(sc[u] - newm); zadd += wgt[u]; }
        z = z * scale + zadd;
        u64 scale2 = pk2(scale, scale);
        u64 wgt2[U];
#pragma unroll
        for (int u = 0; u < U; u++) wgt2[u] = pk2(wgt[u], wgt[u]);
#pragma unroll
        for (int j = 0; j < NC2; j++) {
            u64 a_ = mul2(acc2[j], scale2);
#pragma unroll
            for (int u = 0; u < U; u++) a_ = fma2(wgt2[u], xv2[u][j], a_);
            acc2[j] = a_;
        }
        m = newm;
    }
    for (; i < end; i++) {   // tail
        int s0 = csrc[i];
        float a0 = (lane < 18) ? eac[(size_t)i * 18 + lane] : 0.f;
        const float* p0 = xlr + (size_t)s0 * 2 * C;
        u64 x2[NC2], v2[NC2];
#pragma unroll
        for (int j = 0; j < NC2; j++) {
            int c0 = 2 * (lane + 32 * j);
            float2 xv = (c0 < C) ? *(const float2*)(p0 + c0) : make_float2(0.f, 0.f);
            x2[j] = pk2(xv.x, xv.y);
            v2[j] = add2(x2[j], xrr2[j]);
        }
#pragma unroll
        for (int k = 0; k < 18; k++) {
            float e = __shfl_sync(0xffffffffu, a0, k);
            u64 e2 = pk2(e, e);
#pragma unroll
            for (int j = 0; j < NC2; j++) {
                float2 wv = sWe2[k * 32 * NC2 + lane + 32 * j];
                v2[j] = fma2(e2, pk2(wv.x, wv.y), v2[j]);
            }
        }
        float sc0 = 0.f;
#pragma unroll
        for (int j = 0; j < NC2; j++) {
            float lo, hi;
            upk2(v2[j], lo, hi);
            sc0 += avlo[j] * ((lo > 0.f) ? lo : NEG * lo);
            sc0 += avhi[j] * ((hi > 0.f) ? hi : NEG * hi);
        }
#pragma unroll
        for (int o = 16; o; o >>= 1) sc0 += __shfl_xor_sync(0xffffffffu, sc0, o);
        float newm = fmaxf(m, sc0);
        float scale = __expf(m - newm);
        float w0 = __expf(sc0 - newm);
        z = z * scale + w0;
        u64 scale2 = pk2(scale, scale);
        u64 w02 = pk2(w0, w0);
#pragma unroll
        for (int j = 0; j < NC2; j++)
            acc2[j] = fma2(w02, x2[j], mul2(acc2[j], scale2));
        m = newm;
    }
    float invz = __fdividef(1.0f, z);
#pragma unroll
    for (int j = 0; j < NC2; j++) {
        int c0 = 2 * (lane + 32 * j);
        if (c0 < C) {
            float lo, hi;
            upk2(acc2[j], lo, hi);
            float2 o;
            o.x = fmaxf(lo * invz + bias[c0], 0.f);
            o.y = fmaxf(hi * invz + bias[c0 + 1], 0.f);
            *(float2*)(out + (size_t)n * C + c0) = o;
        }
    }
}

// ---------------- atomic-free mean pool (batch_ids sorted) ----------------
__global__ void k_pool(const float* __restrict__ h, const int* __restrict__ bid,
                       float* __restrict__ pool) {
    int g = blockIdx.x;
    __shared__ int slo, shi;
    if (threadIdx.x == 0) {
        int lo = 0, hi = NN;
        while (lo < hi) { int mid = (lo + hi) >> 1; if (bid[mid] < g) lo = mid + 1; else hi = mid; }
        slo = lo;
        int lo2 = lo; hi = NN;
        while (lo2 < hi) { int mid = (lo2 + hi) >> 1; if (bid[mid] < g + 1) lo2 = mid + 1; else hi = mid; }
        shi = lo2;
    }
    __syncthreads();
    int lo = slo, hi = shi;
    float inv = 1.0f / (float)max(hi - lo, 1);
    for (int c = threadIdx.x; c < 200; c += blockDim.x) {
        float sum = 0.f;
        for (int nn = lo; nn < hi; nn++) sum += h[(size_t)nn * 200 + c];
        pool[g * 200 + c] = sum * inv;
    }
}

// ---------------- launch ----------------
extern "C" void kernel_launch(void* const* d_in, const int* in_sizes, int n_in,
                              void* d_out, int out_size) {
    const float* x   = (const float*)d_in[0];
    const int*   ei  = (const int*)d_in[1];
    const float* ea  = (const float*)d_in[2];
    const int*   bid = (const int*)d_in[3];
    const float* W1l = (const float*)d_in[4];
    const float* b1l = (const float*)d_in[5];
    const float* W1r = (const float*)d_in[6];
    const float* b1r = (const float*)d_in[7];
    const float* W1e = (const float*)d_in[8];
    const float* a1  = (const float*)d_in[9];
    const float* c1  = (const float*)d_in[10];
    const float* W2l = (const float*)d_in[11];
    const float* b2l = (const float*)d_in[12];
    const float* W2r = (const float*)d_in[13];
    const float* b2r = (const float*)d_in[14];
    const float* W2e = (const float*)d_in[15];
    const float* a2  = (const float*)d_in[16];
    const float* c2  = (const float*)d_in[17];
    const float* W3  = (const float*)d_in[18];
    const float* b3  = (const float*)d_in[19];
    const float* F1  = (const float*)d_in[20];
    const float* bf1 = (const float*)d_in[21];
    const float* F2  = (const float*)d_in[22];
    const float* bf2 = (const float*)d_in[23];
    const float* F3  = (const float*)d_in[24];
    const float* bf3 = (const float*)d_in[25];

    float *xlr1, *out1, *xlr2, *out2, *eac, *pool2, *pool3, *y1, *y2;
    int *ints, *off, *doff, *csrc, *pos, *perm;
    cudaGetSymbolAddress((void**)&xlr1,  g_xlr1);
    cudaGetSymbolAddress((void**)&out1,  g_out1);
    cudaGetSymbolAddress((void**)&xlr2,  g_xlr2);
    cudaGetSymbolAddress((void**)&out2,  g_out2);
    cudaGetSymbolAddress((void**)&eac,   g_eac);
    cudaGetSymbolAddress((void**)&ints,  g_ints);
    cudaGetSymbolAddress((void**)&off,   g_off);
    cudaGetSymbolAddress((void**)&doff,  g_doff);
    cudaGetSymbolAddress((void**)&csrc,  g_csrc);
    cudaGetSymbolAddress((void**)&pos,   g_pos);
    cudaGetSymbolAddress((void**)&perm,  g_perm);
    cudaGetSymbolAddress((void**)&pool2, g_pool2);
    cudaGetSymbolAddress((void**)&pool3, g_pool3);
    cudaGetSymbolAddress((void**)&y1,    g_y1);
    cudaGetSymbolAddress((void**)&y2,    g_y2);

    int* cnt  = ints;
    int* cur  = ints + NN;
    int* dh   = ints + 2 * NN;
    int* dcur = ints + 2 * NN + DMAX;

    static cudaStream_t s1 = nullptr, s2 = nullptr;
    static cudaEvent_t evFork = nullptr, evCsr = nullptr, evDeg = nullptr, evOffReady = nullptr;
    if (!s1) {
        cudaStreamCreateWithFlags(&s1, cudaStreamNonBlocking);
        cudaStreamCreateWithFlags(&s2, cudaStreamNonBlocking);
        cudaEventCreateWithFlags(&evFork, cudaEventDisableTiming);
        cudaEventCreateWithFlags(&evCsr, cudaEventDisableTiming);
        cudaEventCreateWithFlags(&evDeg, cudaEventDisableTiming);
        cudaEventCreateWithFlags(&evOffReady, cudaEventDisableTiming);
    }

    const int T = 256;

    // ---- fork: CSR chain on s1, degree-sort on s2, gemm L1 on default ----
    cudaEventRecord(evFork, 0);
    cudaStreamWaitEvent(s1, evFork, 0);

    // s1: CSR build
    cudaMemsetAsync(ints, 0, (2 * NN + 2 * DMAX) * sizeof(int), s1);
    k_hist<<<(EE + NN + T - 1) / T, T, 0, s1>>>(ei, cnt);
    k_scan<<<1, 1024, 0, s1>>>(cnt, off);
    cudaEventRecord(evOffReady, s1);
    k_scatter<<<(E2T + T - 1) / T, T, 0, s1>>>(ei, off, cur, csrc, pos);
    k_eagather<<<(EE * 9 + T - 1) / T, T, 0, s1>>>(ea, pos, eac);
    k_loopattr<<<(NN * 9 + T - 1) / T, T, 0, s1>>>(off, pos, eac);
    cudaEventRecord(evCsr, s1);

    // s2: degree sort (needs only off)
    cudaStreamWaitEvent(s2, evOffReady, 0);
    k_deghist<<<(NN + T - 1) / T, T, 0, s2>>>(off, dh);
    k_dscan<<<1, DMAX, 0, s2>>>(dh, doff);
    k_dscatter<<<(NN + T - 1) / T, T, 0, s2>>>(off, doff, dcur, perm);
    cudaEventRecord(evDeg, s2);

    // default stream: layer-1 GEMM (independent of CSR)
    {
        dim3 g((200 + 63) / 64, (NN + 63) / 64);
        k_gemm2_tc<<<g, 256>>>(x, W1l, W1r, b1l, b1r, xlr1, NN, 16, 100);
    }

    // join
    cudaStreamWaitEvent(0, evCsr, 0);
    cudaStreamWaitEvent(0, evDeg, 0);

    // --- layer 1 GAT (256-thread blocks) ---
    k_gat<100, 2, 8><<<(NN + 7) / 8, 256, 18 * 64 * sizeof(float2)>>>(
        off, csrc, perm, eac, W1e, a1, xlr1, c1, out1);

    // --- layer 2 ---
    {
        dim3 g((400 + 63) / 64, (NN + 63) / 64);
        k_gemm2_tc<<<g, 256>>>(out1, W2l, W2r, b2l, b2r, xlr2, NN, 100, 200);
    }
    // ISOLATED CHANGE vs R13: 128-thread blocks for the high-register C=200 kernel
    // (RF-limited: ~3 blocks/SM -> 12 warps instead of 8)
    k_gat<200, 4, 4><<<(NN + 3) / 4, 128, 18 * 128 * sizeof(float2)>>>(
        off, csrc, perm, eac, W2e, a2, xlr2, c2, out2);

    // --- mean pool, then 200->400 ---
    k_pool<<<GG, 256>>>(out2, bid, pool2);
    {
        dim3 g((400 + 63) / 64, (GG + 63) / 64);
        k_gemm<<<g, 256>>>(pool2, W3, b3, pool3, GG, 200, 400, 0);
    }

    // --- FFN head ---
    {
        dim3 g((200 + 63) / 64, (GG + 63) / 64);
        k_gemm<<<g, 256>>>(pool3, F1, bf1, y1, GG, 400, 200, 1);
    }
    {
        dim3 g((100 + 63) / 64, (GG + 63) / 64);
        k_gemm<<<g, 256>>>(y1, F2, bf2, y2, GG, 200, 100, 1);
    }
    {
        dim3 g((100 + 63) / 64, (GG + 63) / 64);
        k_gemm<<<g, 256>>>(y2, F3, bf3, (float*)d_out, GG, 100, 100, 0);
    }
}